// round 2
// baseline (speedup 1.0000x reference)
#include <cuda_runtime.h>

#define T_OBS 8
#define T_PRE 12
#define BATCH 524288
#define INP 2
#define H 8
#define EMB 16

typedef unsigned long long u64;

// ---------------- packed f32x2 helpers (sm_103a) ----------------
__device__ __forceinline__ u64 fma2(u64 a, u64 b, u64 c) {
    u64 d; asm("fma.rn.f32x2 %0, %1, %2, %3;" : "=l"(d) : "l"(a), "l"(b), "l"(c)); return d;
}
__device__ __forceinline__ u64 mul2(u64 a, u64 b) {
    u64 d; asm("mul.rn.f32x2 %0, %1, %2;" : "=l"(d) : "l"(a), "l"(b)); return d;
}
__device__ __forceinline__ u64 pack2(float lo, float hi) {
    u64 d; asm("mov.b64 %0, {%1, %2};" : "=l"(d) : "f"(lo), "f"(hi)); return d;
}
__device__ __forceinline__ void unpack2(u64 v, float& lo, float& hi) {
    asm("mov.b64 {%0, %1}, %2;" : "=f"(lo), "=f"(hi) : "l"(v));
}

// accurate-enough activations: ex2 + rcp (2 MUFU each), ~1e-7 rel err
__device__ __forceinline__ float sigf(float x) {
    return __fdividef(1.0f, 1.0f + __expf(-x));
}
__device__ __forceinline__ float tanhacc(float x) {
    return fmaf(2.0f, sigf(2.0f * x), -1.0f);
}
__device__ __forceinline__ u64 sig2(u64 v) {
    float a, b; unpack2(v, a, b); return pack2(sigf(a), sigf(b));
}
__device__ __forceinline__ u64 tanh2(u64 v) {
    float a, b; unpack2(v, a, b); return pack2(tanhacc(a), tanhacc(b));
}

// Folded weights, duplicated (w,w) pairs for packed FMA.
// Layout: [phase][unit k][gate q][6 x ulonglong2] = 12 u64:
//   u0=a0 u1=a1 u2=b u3..u10=whh[0..7] u11=pad
__device__ ulonglong2 g_W[2][H][4][6];

__global__ void prep_kernel(const float* __restrict__ W_in, const float* __restrict__ b_in,
                            const float* __restrict__ W_ih_obs, const float* __restrict__ W_hh_obs,
                            const float* __restrict__ b_ih_obs, const float* __restrict__ b_hh_obs,
                            const float* __restrict__ W_ih_pre, const float* __restrict__ W_hh_pre,
                            const float* __restrict__ b_ih_pre, const float* __restrict__ b_hh_pre) {
    int j = threadIdx.x;   // gate row 0..31
    int p = threadIdx.y;   // phase
    const float* W_ih = p ? W_ih_pre : W_ih_obs;
    const float* W_hh = p ? W_hh_pre : W_hh_obs;
    const float* b_ih = p ? b_ih_pre : b_ih_obs;
    const float* b_hh = p ? b_hh_pre : b_hh_obs;

    // fold embedding into gate projection: A = W_ih @ W_in (32x2), b_tot = W_ih@b_in + b_ih + b_hh
    float a0 = 0.f, a1 = 0.f, bb = 0.f;
#pragma unroll
    for (int e = 0; e < EMB; e++) {
        float w = W_ih[j * EMB + e];
        a0 = fmaf(w, W_in[e * INP + 0], a0);
        a1 = fmaf(w, W_in[e * INP + 1], a1);
        bb = fmaf(w, b_in[e], bb);
    }
    bb += b_ih[j] + b_hh[j];

    int q = j / H;   // gate type (i,f,g,o)
    int k = j % H;   // unit

    u64 vals[12];
    vals[0] = pack2(a0, a0);
    vals[1] = pack2(a1, a1);
    vals[2] = pack2(bb, bb);
#pragma unroll
    for (int m = 0; m < H; m++) {
        float w = W_hh[j * H + m];
        vals[3 + m] = pack2(w, w);
    }
    vals[11] = 0ull;
#pragma unroll
    for (int m = 0; m < 6; m++) {
        ulonglong2 v; v.x = vals[2 * m]; v.y = vals[2 * m + 1];
        g_W[p][k][q][m] = v;
    }
}

template <int T>
__device__ __forceinline__ void lstm_scan2(const float* __restrict__ xin, int e0,
                                           const ulonglong2 (*__restrict__ W)[4][6],
                                           u64 hp[H], u64 cp[H]) {
#pragma unroll 1
    for (int t = 0; t < T; t++) {
        // two consecutive elements' inputs: (x0a,x1a,x0b,x1b)
        float4 xv = *(const float4*)(xin + ((size_t)t * BATCH + e0) * INP);
        u64 x0 = pack2(xv.x, xv.z);
        u64 x1 = pack2(xv.y, xv.w);
        u64 hn[H];
#pragma unroll
        for (int k = 0; k < H; k++) {
            u64 acc[4];
#pragma unroll
            for (int q = 0; q < 4; q++) {
                const ulonglong2* Wr = W[k][q];
                ulonglong2 v0 = Wr[0], v1 = Wr[1], v2 = Wr[2];
                ulonglong2 v3 = Wr[3], v4 = Wr[4], v5 = Wr[5];
                u64 a = fma2(v0.y, x1, fma2(v0.x, x0, v1.x));
                a = fma2(v1.y, hp[0], a);
                a = fma2(v2.x, hp[1], a);
                a = fma2(v2.y, hp[2], a);
                a = fma2(v3.x, hp[3], a);
                a = fma2(v3.y, hp[4], a);
                a = fma2(v4.x, hp[5], a);
                a = fma2(v4.y, hp[6], a);
                a = fma2(v5.x, hp[7], a);
                acc[q] = a;
            }
            u64 ig = sig2(acc[0]);
            u64 fg = sig2(acc[1]);
            u64 gg = tanh2(acc[2]);
            u64 og = sig2(acc[3]);
            cp[k] = fma2(fg, cp[k], mul2(ig, gg));
            hn[k] = mul2(og, tanh2(cp[k]));
        }
#pragma unroll
        for (int k = 0; k < H; k++) hp[k] = hn[k];
    }
}

__global__ __launch_bounds__(256, 2) void lstm_kernel(
    const float* __restrict__ obs, const float* __restrict__ pre,
    const float* __restrict__ h0, const float* __restrict__ c0,
    const float* __restrict__ c0p, float* __restrict__ out)
{
    __shared__ ulonglong2 sW[2][H][4][6];
    {
        const float* src = (const float*)g_W;
        float* dst = (float*)sW;
        constexpr int NF = (int)(sizeof(g_W) / sizeof(float));
        for (int i = threadIdx.x; i < NF; i += 256) dst[i] = src[i];
    }
    __syncthreads();

    const int gid = blockIdx.x * 256 + threadIdx.x;
    const int e0 = gid * 2;   // this thread handles elements e0, e0+1

    u64 hp[H], cp[H];
    {
        const float4* ha = (const float4*)(h0 + (size_t)e0 * H);  // 4 x float4 covers both elems
        float4 a0 = ha[0], a1 = ha[1], b0 = ha[2], b1 = ha[3];
        hp[0] = pack2(a0.x, b0.x); hp[1] = pack2(a0.y, b0.y);
        hp[2] = pack2(a0.z, b0.z); hp[3] = pack2(a0.w, b0.w);
        hp[4] = pack2(a1.x, b1.x); hp[5] = pack2(a1.y, b1.y);
        hp[6] = pack2(a1.z, b1.z); hp[7] = pack2(a1.w, b1.w);
        const float4* ca = (const float4*)(c0 + (size_t)e0 * H);
        a0 = ca[0]; a1 = ca[1]; b0 = ca[2]; b1 = ca[3];
        cp[0] = pack2(a0.x, b0.x); cp[1] = pack2(a0.y, b0.y);
        cp[2] = pack2(a0.z, b0.z); cp[3] = pack2(a0.w, b0.w);
        cp[4] = pack2(a1.x, b1.x); cp[5] = pack2(a1.y, b1.y);
        cp[6] = pack2(a1.z, b1.z); cp[7] = pack2(a1.w, b1.w);
    }

    // Phase 1: observation scan
    lstm_scan2<T_OBS>(obs, e0, sW[0], hp, cp);

    // c_out: out[j*B + e] — packed pair (e0,e0+1) is exactly one 8B store
#pragma unroll
    for (int j = 0; j < H; j++)
        *(u64*)(out + (size_t)j * BATCH + e0) = hp[j];

    // Phase 2: cell state reset to c0_pre, h carries over
    {
        const float4* ca = (const float4*)(c0p + (size_t)e0 * H);
        float4 a0 = ca[0], a1 = ca[1], b0 = ca[2], b1 = ca[3];
        cp[0] = pack2(a0.x, b0.x); cp[1] = pack2(a0.y, b0.y);
        cp[2] = pack2(a0.z, b0.z); cp[3] = pack2(a0.w, b0.w);
        cp[4] = pack2(a1.x, b1.x); cp[5] = pack2(a1.y, b1.y);
        cp[6] = pack2(a1.z, b1.z); cp[7] = pack2(a1.w, b1.w);
    }
    lstm_scan2<T_PRE>(pre, e0, sW[1], hp, cp);

#pragma unroll
    for (int j = 0; j < H; j++)
        *(u64*)(out + (size_t)(H + j) * BATCH + e0) = hp[j];
}

extern "C" void kernel_launch(void* const* d_in, const int* in_sizes, int n_in,
                              void* d_out, int out_size) {
    const float* obs  = (const float*)d_in[0];
    const float* pre  = (const float*)d_in[1];
    const float* h0   = (const float*)d_in[2];
    const float* c0   = (const float*)d_in[3];
    const float* c0p  = (const float*)d_in[4];

    prep_kernel<<<1, dim3(32, 2)>>>(
        (const float*)d_in[5],  (const float*)d_in[6],
        (const float*)d_in[7],  (const float*)d_in[8],
        (const float*)d_in[9],  (const float*)d_in[10],
        (const float*)d_in[11], (const float*)d_in[12],
        (const float*)d_in[13], (const float*)d_in[14]);

    lstm_kernel<<<(BATCH / 2) / 256, 256>>>(obs, pre, h0, c0, c0p, (float*)d_out);
}

// round 3
// speedup vs baseline: 3.5887x; 3.5887x over previous
#include <cuda_runtime.h>

#define T_OBS 8
#define T_PRE 12
#define BATCH 524288
#define INP 2
#define H 8
#define EMB 16

typedef unsigned long long u64;

// ---------------- packed f32x2 + fast activation helpers (sm_103a) ----------------
__device__ __forceinline__ u64 fma2(u64 a, u64 b, u64 c) {
    u64 d; asm("fma.rn.f32x2 %0, %1, %2, %3;" : "=l"(d) : "l"(a), "l"(b), "l"(c)); return d;
}
__device__ __forceinline__ u64 pack2(float lo, float hi) {
    u64 d; asm("mov.b64 %0, {%1, %2};" : "=l"(d) : "f"(lo), "f"(hi)); return d;
}
__device__ __forceinline__ void unpack2(u64 v, float& lo, float& hi) {
    asm("mov.b64 {%0, %1}, %2;" : "=f"(lo), "=f"(hi) : "l"(v));
}
__device__ __forceinline__ float tanh_ap(float x) {
    float y; asm("tanh.approx.f32 %0, %1;" : "=f"(y) : "f"(x)); return y;
}
__device__ __forceinline__ float sig_ap(float x) {
    // sigmoid(x) = 0.5 + 0.5*tanh(0.5*x)  -> 1 MUFU + 2 fma-pipe ops
    return fmaf(0.5f, tanh_ap(0.5f * x), 0.5f);
}

// Folded + gate-paired weights.
// Per phase, per unit k, per pair p (p0 = gates (i,f), p1 = gates (g,o)):
//   u0 = (A0_lo, A0_hi)  u1 = (A1_lo, A1_hi)  u2 = (b_lo, b_hi)
//   u3..u10 = (whh_m_lo, whh_m_hi) for m=0..7,  u11 = pad
// stored as 6 x ulonglong2 for LDS.128.
__device__ float      g_rows[2][32][11];      // prep scratch: a0, a1, b, whh[0..7]
__device__ ulonglong2 g_W[2][H][2][6];

__global__ void prep_kernel(const float* __restrict__ W_in, const float* __restrict__ b_in,
                            const float* __restrict__ W_ih_obs, const float* __restrict__ W_hh_obs,
                            const float* __restrict__ b_ih_obs, const float* __restrict__ b_hh_obs,
                            const float* __restrict__ W_ih_pre, const float* __restrict__ W_hh_pre,
                            const float* __restrict__ b_ih_pre, const float* __restrict__ b_hh_pre) {
    int j = threadIdx.x;   // gate row 0..31
    int p = threadIdx.y;   // phase
    const float* W_ih = p ? W_ih_pre : W_ih_obs;
    const float* W_hh = p ? W_hh_pre : W_hh_obs;
    const float* b_ih = p ? b_ih_pre : b_ih_obs;
    const float* b_hh = p ? b_hh_pre : b_hh_obs;

    // fold embedding: A = W_ih @ W_in (32x2), b_tot = W_ih@b_in + b_ih + b_hh
    float a0 = 0.f, a1 = 0.f, bb = 0.f;
#pragma unroll
    for (int e = 0; e < EMB; e++) {
        float w = W_ih[j * EMB + e];
        a0 = fmaf(w, W_in[e * INP + 0], a0);
        a1 = fmaf(w, W_in[e * INP + 1], a1);
        bb = fmaf(w, b_in[e], bb);
    }
    g_rows[p][j][0] = a0;
    g_rows[p][j][1] = a1;
    g_rows[p][j][2] = bb + b_ih[j] + b_hh[j];
#pragma unroll
    for (int m = 0; m < H; m++)
        g_rows[p][j][3 + m] = W_hh[j * H + m];

    __syncthreads();

    // pack gate pairs: threads j = 0..15 per phase
    if (j < 16) {
        int k  = j % H;       // unit
        int pr = j / H;       // pair: 0 -> (i,f) rows (k, 8+k); 1 -> (g,o) rows (16+k, 24+k)
        int rlo = pr ? (16 + k) : k;
        int rhi = pr ? (24 + k) : (8 + k);
        u64 vals[12];
#pragma unroll
        for (int m = 0; m < 11; m++)
            vals[m] = pack2(g_rows[p][rlo][m], g_rows[p][rhi][m]);
        vals[11] = 0ull;
#pragma unroll
        for (int m = 0; m < 6; m++) {
            ulonglong2 v; v.x = vals[2 * m]; v.y = vals[2 * m + 1];
            g_W[p][k][pr][m] = v;
        }
    }
}

template <int T>
__device__ __forceinline__ void lstm_scan(const float* __restrict__ xin, int e,
                                          const ulonglong2 (*__restrict__ W)[2][6],
                                          float h[H], float c[H], u64 hd[H]) {
#pragma unroll 1
    for (int t = 0; t < T; t++) {
        float2 x = *(const float2*)(xin + ((size_t)t * BATCH + e) * INP);
        u64 x0 = pack2(x.x, x.x);
        u64 x1 = pack2(x.y, x.y);
        float hn[H];
#pragma unroll
        for (int k = 0; k < H; k++) {
            u64 acc[2];
#pragma unroll
            for (int pr = 0; pr < 2; pr++) {
                const ulonglong2* Wr = W[k][pr];
                ulonglong2 v0 = Wr[0], v1 = Wr[1], v2 = Wr[2];
                ulonglong2 v3 = Wr[3], v4 = Wr[4], v5 = Wr[5];
                u64 a = fma2(v0.y, x1, fma2(v0.x, x0, v1.x));
                a = fma2(v1.y, hd[0], a);
                a = fma2(v2.x, hd[1], a);
                a = fma2(v2.y, hd[2], a);
                a = fma2(v3.x, hd[3], a);
                a = fma2(v3.y, hd[4], a);
                a = fma2(v4.x, hd[5], a);
                a = fma2(v4.y, hd[6], a);
                a = fma2(v5.x, hd[7], a);
                acc[pr] = a;
            }
            float gi, gf, gg, go;
            unpack2(acc[0], gi, gf);
            unpack2(acc[1], gg, go);
            float ig = sig_ap(gi);
            float fg = sig_ap(gf);
            float gv = tanh_ap(gg);
            float og = sig_ap(go);
            c[k] = fmaf(fg, c[k], ig * gv);
            hn[k] = og * tanh_ap(c[k]);
        }
#pragma unroll
        for (int k = 0; k < H; k++) {
            h[k]  = hn[k];
            hd[k] = pack2(hn[k], hn[k]);
        }
    }
}

__global__ __launch_bounds__(256, 2) void lstm_kernel(
    const float* __restrict__ obs, const float* __restrict__ pre,
    const float* __restrict__ h0, const float* __restrict__ c0,
    const float* __restrict__ c0p, float* __restrict__ out)
{
    __shared__ ulonglong2 sW[2][H][2][6];
    {
        const float* src = (const float*)g_W;
        float* dst = (float*)sW;
        constexpr int NF = (int)(sizeof(g_W) / sizeof(float));
        for (int i = threadIdx.x; i < NF; i += 256) dst[i] = src[i];
    }
    __syncthreads();

    const int e = blockIdx.x * 256 + threadIdx.x;

    float h[H], c[H];
    u64 hd[H];
    {
        float4 a = *(const float4*)(h0 + (size_t)e * H);
        float4 b = *(const float4*)(h0 + (size_t)e * H + 4);
        h[0]=a.x; h[1]=a.y; h[2]=a.z; h[3]=a.w; h[4]=b.x; h[5]=b.y; h[6]=b.z; h[7]=b.w;
        a = *(const float4*)(c0 + (size_t)e * H);
        b = *(const float4*)(c0 + (size_t)e * H + 4);
        c[0]=a.x; c[1]=a.y; c[2]=a.z; c[3]=a.w; c[4]=b.x; c[5]=b.y; c[6]=b.z; c[7]=b.w;
    }
#pragma unroll
    for (int k = 0; k < H; k++) hd[k] = pack2(h[k], h[k]);

    // Phase 1: observation scan
    lstm_scan<T_OBS>(obs, e, sW[0], h, c, hd);

    // c_out: out[j*B + e] = h[j]
#pragma unroll
    for (int j = 0; j < H; j++)
        out[(size_t)j * BATCH + e] = h[j];

    // Phase 2: cell state reset to c0_pre, h carries over
    {
        float4 a = *(const float4*)(c0p + (size_t)e * H);
        float4 b = *(const float4*)(c0p + (size_t)e * H + 4);
        c[0]=a.x; c[1]=a.y; c[2]=a.z; c[3]=a.w; c[4]=b.x; c[5]=b.y; c[6]=b.z; c[7]=b.w;
    }
    lstm_scan<T_PRE>(pre, e, sW[1], h, c, hd);

#pragma unroll
    for (int j = 0; j < H; j++)
        out[(size_t)(H + j) * BATCH + e] = h[j];
}

extern "C" void kernel_launch(void* const* d_in, const int* in_sizes, int n_in,
                              void* d_out, int out_size) {
    const float* obs  = (const float*)d_in[0];
    const float* pre  = (const float*)d_in[1];
    const float* h0   = (const float*)d_in[2];
    const float* c0   = (const float*)d_in[3];
    const float* c0p  = (const float*)d_in[4];

    prep_kernel<<<1, dim3(32, 2)>>>(
        (const float*)d_in[5],  (const float*)d_in[6],
        (const float*)d_in[7],  (const float*)d_in[8],
        (const float*)d_in[9],  (const float*)d_in[10],
        (const float*)d_in[11], (const float*)d_in[12],
        (const float*)d_in[13], (const float*)d_in[14]);

    lstm_kernel<<<BATCH / 256, 256>>>(obs, pre, h0, c0, c0p, (float*)d_out);
}

// round 4
// speedup vs baseline: 7.4338x; 2.0714x over previous
#include <cuda_runtime.h>

#define T_OBS 8
#define T_PRE 12
#define BATCH 524288
#define INP 2
#define H 8
#define EMB 16

typedef unsigned long long u64;

// ---------------- packed f32x2 + fast activation helpers (sm_103a) ----------------
__device__ __forceinline__ u64 fma2(u64 a, u64 b, u64 c) {
    u64 d; asm("fma.rn.f32x2 %0, %1, %2, %3;" : "=l"(d) : "l"(a), "l"(b), "l"(c)); return d;
}
__device__ __forceinline__ u64 pack2(float lo, float hi) {
    u64 d; asm("mov.b64 %0, {%1, %2};" : "=l"(d) : "f"(lo), "f"(hi)); return d;
}
__device__ __forceinline__ void unpack2(u64 v, float& lo, float& hi) {
    asm("mov.b64 {%0, %1}, %2;" : "=f"(lo), "=f"(hi) : "l"(v));
}
__device__ __forceinline__ float tanh_ap(float x) {
    float y; asm("tanh.approx.f32 %0, %1;" : "=f"(y) : "f"(x)); return y;
}
__device__ __forceinline__ float sig_ap(float x) {
    // sigmoid(x) = 0.5 + 0.5*tanh(0.5*x)  -> 1 MUFU + 2 fma-pipe ops
    return fmaf(0.5f, tanh_ap(0.5f * x), 0.5f);
}

// Folded + gate-paired weights.
// Per phase, per unit k, per pair p (p0 = gates (i,f), p1 = gates (g,o)):
//   u0 = (A0_lo, A0_hi)  u1 = (A1_lo, A1_hi)  u2 = (b_lo, b_hi)
//   u3..u10 = (whh_m_lo, whh_m_hi) for m=0..7,  u11 = pad
__device__ float      g_rows[2][32][11];
__device__ ulonglong2 g_W[2][H][2][6];

__global__ void prep_kernel(const float* __restrict__ W_in, const float* __restrict__ b_in,
                            const float* __restrict__ W_ih_obs, const float* __restrict__ W_hh_obs,
                            const float* __restrict__ b_ih_obs, const float* __restrict__ b_hh_obs,
                            const float* __restrict__ W_ih_pre, const float* __restrict__ W_hh_pre,
                            const float* __restrict__ b_ih_pre, const float* __restrict__ b_hh_pre) {
    int j = threadIdx.x;   // gate row 0..31
    int p = threadIdx.y;   // phase
    const float* W_ih = p ? W_ih_pre : W_ih_obs;
    const float* W_hh = p ? W_hh_pre : W_hh_obs;
    const float* b_ih = p ? b_ih_pre : b_ih_obs;
    const float* b_hh = p ? b_hh_pre : b_hh_obs;

    // fold embedding: A = W_ih @ W_in (32x2), b_tot = W_ih@b_in + b_ih + b_hh
    float a0 = 0.f, a1 = 0.f, bb = 0.f;
#pragma unroll
    for (int e = 0; e < EMB; e++) {
        float w = W_ih[j * EMB + e];
        a0 = fmaf(w, W_in[e * INP + 0], a0);
        a1 = fmaf(w, W_in[e * INP + 1], a1);
        bb = fmaf(w, b_in[e], bb);
    }
    g_rows[p][j][0] = a0;
    g_rows[p][j][1] = a1;
    g_rows[p][j][2] = bb + b_ih[j] + b_hh[j];
#pragma unroll
    for (int m = 0; m < H; m++)
        g_rows[p][j][3 + m] = W_hh[j * H + m];

    __syncthreads();

    if (j < 16) {
        int k  = j % H;       // unit
        int pr = j / H;       // pair: 0 -> (i,f) rows (k, 8+k); 1 -> (g,o) rows (16+k, 24+k)
        int rlo = pr ? (16 + k) : k;
        int rhi = pr ? (24 + k) : (8 + k);
        u64 vals[12];
#pragma unroll
        for (int m = 0; m < 11; m++)
            vals[m] = pack2(g_rows[p][rlo][m], g_rows[p][rhi][m]);
        vals[11] = 0ull;
#pragma unroll
        for (int m = 0; m < 6; m++) {
            ulonglong2 v; v.x = vals[2 * m]; v.y = vals[2 * m + 1];
            g_W[p][k][pr][m] = v;
        }
    }
}

// one gate-pair accumulation: 11 fma2, weights loaded just-in-time (short live ranges)
__device__ __forceinline__ u64 gate_pair(const ulonglong2* __restrict__ Wr,
                                         u64 x0, u64 x1, const u64 hd[H]) {
    ulonglong2 v0 = Wr[0];
    ulonglong2 v1 = Wr[1];
    u64 a = fma2(v0.x, x0, v1.x);
    a = fma2(v0.y, x1, a);
    a = fma2(v1.y, hd[0], a);
    ulonglong2 v2 = Wr[2];
    a = fma2(v2.x, hd[1], a);
    a = fma2(v2.y, hd[2], a);
    ulonglong2 v3 = Wr[3];
    a = fma2(v3.x, hd[3], a);
    a = fma2(v3.y, hd[4], a);
    ulonglong2 v4 = Wr[4];
    a = fma2(v4.x, hd[5], a);
    a = fma2(v4.y, hd[6], a);
    ulonglong2 v5 = Wr[5];
    a = fma2(v5.x, hd[7], a);
    return a;
}

template <int T>
__device__ __forceinline__ void lstm_scan(const float* __restrict__ xin, int e,
                                          const ulonglong2 (*__restrict__ W)[2][6],
                                          u64 hd[H], float c[H]) {
    // software-pipelined x load (depth 1): hide GMEM latency behind step compute
    float2 xv = *(const float2*)(xin + (size_t)e * INP);
#pragma unroll 1
    for (int t = 0; t < T; t++) {
        u64 x0 = pack2(xv.x, xv.x);
        u64 x1 = pack2(xv.y, xv.y);
        if (t + 1 < T)
            xv = *(const float2*)(xin + ((size_t)(t + 1) * BATCH + e) * INP);
        u64 hn[H];
#pragma unroll 2
        for (int k = 0; k < H; k++) {
            u64 acc0 = gate_pair(W[k][0], x0, x1, hd);  // (i, f)
            u64 acc1 = gate_pair(W[k][1], x0, x1, hd);  // (g, o)
            float gi, gf, gg, go;
            unpack2(acc0, gi, gf);
            unpack2(acc1, gg, go);
            float ig = sig_ap(gi);
            float fg = sig_ap(gf);
            float gv = tanh_ap(gg);
            float og = sig_ap(go);
            float cn = fmaf(fg, c[k], ig * gv);
            c[k] = cn;
            float hv = og * tanh_ap(cn);
            hn[k] = pack2(hv, hv);
        }
#pragma unroll
        for (int k = 0; k < H; k++) hd[k] = hn[k];
    }
}

__global__ __launch_bounds__(256, 2) void lstm_kernel(
    const float* __restrict__ obs, const float* __restrict__ pre,
    const float* __restrict__ h0, const float* __restrict__ c0,
    const float* __restrict__ c0p, float* __restrict__ out)
{
    __shared__ ulonglong2 sW[2][H][2][6];
    {
        const float* src = (const float*)g_W;
        float* dst = (float*)sW;
        constexpr int NF = (int)(sizeof(g_W) / sizeof(float));
        for (int i = threadIdx.x; i < NF; i += 256) dst[i] = src[i];
    }
    __syncthreads();

    const int e = blockIdx.x * 256 + threadIdx.x;

    u64 hd[H];
    float c[H];
    {
        float4 a = *(const float4*)(h0 + (size_t)e * H);
        float4 b = *(const float4*)(h0 + (size_t)e * H + 4);
        hd[0] = pack2(a.x, a.x); hd[1] = pack2(a.y, a.y);
        hd[2] = pack2(a.z, a.z); hd[3] = pack2(a.w, a.w);
        hd[4] = pack2(b.x, b.x); hd[5] = pack2(b.y, b.y);
        hd[6] = pack2(b.z, b.z); hd[7] = pack2(b.w, b.w);
        a = *(const float4*)(c0 + (size_t)e * H);
        b = *(const float4*)(c0 + (size_t)e * H + 4);
        c[0]=a.x; c[1]=a.y; c[2]=a.z; c[3]=a.w; c[4]=b.x; c[5]=b.y; c[6]=b.z; c[7]=b.w;
    }

    // Phase 1: observation scan
    lstm_scan<T_OBS>(obs, e, sW[0], hd, c);

    // c_out: out[j*B + e] = h[j]
#pragma unroll
    for (int j = 0; j < H; j++) {
        float lo, hi; unpack2(hd[j], lo, hi);
        out[(size_t)j * BATCH + e] = lo;
    }

    // Phase 2: cell state reset to c0_pre, h carries over
    {
        float4 a = *(const float4*)(c0p + (size_t)e * H);
        float4 b = *(const float4*)(c0p + (size_t)e * H + 4);
        c[0]=a.x; c[1]=a.y; c[2]=a.z; c[3]=a.w; c[4]=b.x; c[5]=b.y; c[6]=b.z; c[7]=b.w;
    }
    lstm_scan<T_PRE>(pre, e, sW[1], hd, c);

#pragma unroll
    for (int j = 0; j < H; j++) {
        float lo, hi; unpack2(hd[j], lo, hi);
        out[(size_t)(H + j) * BATCH + e] = lo;
    }
}

extern "C" void kernel_launch(void* const* d_in, const int* in_sizes, int n_in,
                              void* d_out, int out_size) {
    const float* obs  = (const float*)d_in[0];
    const float* pre  = (const float*)d_in[1];
    const float* h0   = (const float*)d_in[2];
    const float* c0   = (const float*)d_in[3];
    const float* c0p  = (const float*)d_in[4];

    prep_kernel<<<1, dim3(32, 2)>>>(
        (const float*)d_in[5],  (const float*)d_in[6],
        (const float*)d_in[7],  (const float*)d_in[8],
        (const float*)d_in[9],  (const float*)d_in[10],
        (const float*)d_in[11], (const float*)d_in[12],
        (const float*)d_in[13], (const float*)d_in[14]);

    lstm_kernel<<<BATCH / 256, 256>>>(obs, pre, h0, c0, c0p, (float*)d_out);
}